// round 7
// baseline (speedup 1.0000x reference)
#include <cuda_runtime.h>
#include <cstdint>
#include <cstddef>

#define B_    16
#define N_    1024
#define D_    256
#define K_    16
#define S_    512
#define M_TOT (B_*N_)          /* 16384 */
#define KS_   (K_*S_)          /* 8192  */
#define ZQ_SIZE   (M_TOT*D_)   /* 4194304 */
#define PROB_SIZE ((size_t)M_TOT*S_) /* 8388608 */

// ---------------- scratch ------------------------------------------------------
__device__ float  g_scratch[(size_t)M_TOT * KS_];   // logits (512 MB)
__device__ float2 g_wS[(size_t)M_TOT * KS_];        // W split hi/lo (1 GB)
__device__ float2 g_zeS[(size_t)M_TOT * D_];        // ze split (32 MB)
__device__ float2 g_bkS[(size_t)KS_ * D_];          // books split (16 MB)
__device__ float  g_z2[M_TOT];
__device__ float  g_b2[KS_];
__device__ float  g_cprobs[B_ * K_];
__device__ float  g_prec[2];

// ---------------- threefry2x32-20 (JAX partitionable) --------------------------
__device__ __forceinline__ void d_tf(uint32_t k0, uint32_t k1,
                                     uint32_t x0, uint32_t x1,
                                     uint32_t& o0, uint32_t& o1) {
    uint32_t ks2 = k0 ^ k1 ^ 0x1BD11BDAu;
    x0 += k0; x1 += k1;
#define TFR(r) { x0 += x1; x1 = __funnelshift_l(x1, x1, r); x1 ^= x0; }
    TFR(13) TFR(15) TFR(26) TFR(6)   x0 += k1;  x1 += ks2 + 1u;
    TFR(17) TFR(29) TFR(16) TFR(24)  x0 += ks2; x1 += k0  + 2u;
    TFR(13) TFR(15) TFR(26) TFR(6)   x0 += k0;  x1 += k1  + 3u;
    TFR(17) TFR(29) TFR(16) TFR(24)  x0 += k1;  x1 += ks2 + 4u;
    TFR(13) TFR(15) TFR(26) TFR(6)   x0 += ks2; x1 += k0  + 5u;
#undef TFR
    o0 = x0; o1 = x1;
}

__device__ __forceinline__ uint32_t d_bits32(uint32_t k0, uint32_t k1, uint32_t i) {
    uint32_t o0, o1;
    d_tf(k0, k1, 0u, i, o0, o1);
    return o0 ^ o1;
}

__device__ __forceinline__ float bits_to_unit(uint32_t b) {
    return fmaxf(0.0f, __uint_as_float((b >> 9) | 0x3f800000u) - 1.0f);
}
__device__ __forceinline__ float gumbel_of(float u) {
    return -logf(-logf(u + 1e-10f) + 1e-10f);
}

// ---------------- tf32 helpers --------------------------------------------------
__device__ __forceinline__ uint32_t f2tf(float x) {
    uint32_t r;
    asm("cvt.rna.tf32.f32 %0, %1;" : "=r"(r) : "f"(x));
    return r;
}
__device__ __forceinline__ float2 split2(float x) {
    uint32_t hi = f2tf(x);
    uint32_t lo = f2tf(x - __uint_as_float(hi));
    return make_float2(__uint_as_float(hi), __uint_as_float(lo));
}
__device__ __forceinline__ void mma_tf32(float* c, const uint32_t* a, const uint32_t* b) {
    asm volatile(
        "mma.sync.aligned.m16n8k8.row.col.f32.tf32.tf32.f32 "
        "{%0,%1,%2,%3}, {%4,%5,%6,%7}, {%8,%9}, {%0,%1,%2,%3};"
        : "+f"(c[0]), "+f"(c[1]), "+f"(c[2]), "+f"(c[3])
        : "r"(a[0]), "r"(a[1]), "r"(a[2]), "r"(a[3]), "r"(b[0]), "r"(b[1]));
}

__device__ __forceinline__ void cp16(void* smem, const void* gmem) {
    unsigned s = (unsigned)__cvta_generic_to_shared(smem);
    asm volatile("cp.async.cg.shared.global [%0], [%1], 16;" :: "r"(s), "l"(gmem));
}
#define CP_COMMIT asm volatile("cp.async.commit_group;")
#define CP_WAIT1  asm volatile("cp.async.wait_group 1;")
#define CP_WAIT0  asm volatile("cp.async.wait_group 0;")

// ---------------- tiny kernels ---------------------------------------------------
__global__ void k_scalars(const float* __restrict__ lpq,
                          const float* __restrict__ lpqc,
                          float* __restrict__ out_scalar) {
    float pq   = 1.0f + expf(lpq[0]);
    float prec = 0.5f / fmaxf(pq, 1e-10f);
    float pqc  = 1.0f + expf(lpqc[0]);
    float precc= 0.5f / fmaxf(pqc, 1e-10f);
    g_prec[0] = prec;
    g_prec[1] = precc;
    out_scalar[0] = prec;
}

__global__ void k_cprobs(const float* __restrict__ c_logits,
                         uint32_t k0, uint32_t k1) {
    __shared__ float lg[256];
    int t = threadIdx.x;
    float u = bits_to_unit(d_bits32(k0, k1, (uint32_t)t));
    float pqc = g_prec[1];
    lg[t] = (c_logits[t] * pqc + gumbel_of(u)) * 2.0f;
    __syncthreads();
    if (t < 16) {
        float mx = -1e30f;
        for (int j = 0; j < 16; j++) mx = fmaxf(mx, lg[t * 16 + j]);
        float e[16], sm = 0.0f;
        for (int j = 0; j < 16; j++) { e[j] = expf(lg[t * 16 + j] - mx); sm += e[j]; }
        for (int j = 0; j < 16; j++) g_cprobs[t * 16 + j] = e[j] / sm;
    }
}

__global__ void k_norms(const float* __restrict__ ze,
                        const float* __restrict__ books) {
    int warps = (gridDim.x * blockDim.x) >> 5;
    int w     = (blockIdx.x * blockDim.x + threadIdx.x) >> 5;
    int lane  = threadIdx.x & 31;
    for (int r = w; r < M_TOT + KS_; r += warps) {
        const float4* p = (r < M_TOT)
            ? (const float4*)(ze + (size_t)r * D_)
            : (const float4*)(books + (size_t)(r - M_TOT) * D_);
        float s = 0.0f;
#pragma unroll
        for (int j = 0; j < 2; j++) {
            float4 v = p[lane + j * 32];
            s += v.x * v.x + v.y * v.y + v.z * v.z + v.w * v.w;
        }
#pragma unroll
        for (int o = 16; o; o >>= 1) s += __shfl_xor_sync(0xffffffffu, s, o);
        if (lane == 0) { if (r < M_TOT) g_z2[r] = s; else g_b2[r - M_TOT] = s; }
    }
}

// pre-split ze and books into interleaved tf32 (hi, lo) pairs
__global__ void k_split(const float* __restrict__ ze,
                        const float* __restrict__ books) {
    const int MZ = M_TOT * D_;
    const int TOT = MZ + KS_ * D_;
    for (int i = blockIdx.x * blockDim.x + threadIdx.x; i < TOT;
         i += gridDim.x * blockDim.x) {
        if (i < MZ) g_zeS[i] = split2(ze[i]);
        else        g_bkS[i - MZ] = split2(books[i - MZ]);
    }
}

// ============ GEMM1 (tf32 TC): scratch = (2*ze.booksT - z2 - b2)*prec ==========
#define P1 10   /* pitch in float2, BK=8 + 2 pad */
__global__ __launch_bounds__(256, 2)
void k_gemm1_tc(void) {
    __shared__ float2 As[2][128 * P1];
    __shared__ float2 Bs[2][128 * P1];
    const int t = threadIdx.x;
    const int m0 = blockIdx.y * 128, n0 = blockIdx.x * 128;
    const int wid = t >> 5, lane = t & 31;
    const int wm = wid & 1, wn = wid >> 1;          // 2 x 4 warp grid
    const int gr = lane >> 2, ct = lane & 3;

    float acc[4][4][4] = {};

    auto issue = [&](int kt, int st) {
#pragma unroll
        for (int i = 0; i < 2; i++) {
            int c   = t + i * 256;          // 512 chunks: 128 rows x 4 chunks
            int row = c >> 2;
            int k2  = (c & 3) << 1;         // float2 col
            cp16(&As[st][row * P1 + k2], g_zeS + (size_t)(m0 + row) * D_ + kt * 8 + k2);
            cp16(&Bs[st][row * P1 + k2], g_bkS + (size_t)(n0 + row) * D_ + kt * 8 + k2);
        }
        CP_COMMIT;
    };

    const int T = D_ / 8;        // 32
    issue(0, 0);
    issue(1, 1);
    for (int kt = 0; kt < T; kt++) {
        if (kt + 1 < T) { CP_WAIT1; } else { CP_WAIT0; }
        __syncthreads();
        const int st = kt & 1;
        uint32_t ah[4][4], al[4][4], bh[4][2], bl[4][2];
#pragma unroll
        for (int f = 0; f < 4; f++) {
            int r = wm * 64 + f * 16 + gr;
            float2 v;
            v = As[st][r * P1 + ct];           ah[f][0] = __float_as_uint(v.x); al[f][0] = __float_as_uint(v.y);
            v = As[st][(r + 8) * P1 + ct];     ah[f][1] = __float_as_uint(v.x); al[f][1] = __float_as_uint(v.y);
            v = As[st][r * P1 + ct + 4];       ah[f][2] = __float_as_uint(v.x); al[f][2] = __float_as_uint(v.y);
            v = As[st][(r + 8) * P1 + ct + 4]; ah[f][3] = __float_as_uint(v.x); al[f][3] = __float_as_uint(v.y);
        }
#pragma unroll
        for (int j = 0; j < 4; j++) {
            int n = wn * 32 + j * 8 + gr;
            float2 v;
            v = Bs[st][n * P1 + ct];           bh[j][0] = __float_as_uint(v.x); bl[j][0] = __float_as_uint(v.y);
            v = Bs[st][n * P1 + ct + 4];       bh[j][1] = __float_as_uint(v.x); bl[j][1] = __float_as_uint(v.y);
        }
#pragma unroll
        for (int f = 0; f < 4; f++)
#pragma unroll
            for (int j = 0; j < 4; j++) {
                mma_tf32(acc[f][j], ah[f], bh[j]);
                mma_tf32(acc[f][j], ah[f], bl[j]);
                mma_tf32(acc[f][j], al[f], bh[j]);
            }
        __syncthreads();
        if (kt + 2 < T) issue(kt + 2, st);
    }

    const float prec = g_prec[0];
#pragma unroll
    for (int f = 0; f < 4; f++) {
        int m = m0 + wm * 64 + f * 16 + gr;
        float z2a = g_z2[m], z2b = g_z2[m + 8];
#pragma unroll
        for (int j = 0; j < 4; j++) {
            int n = n0 + wn * 32 + j * 8 + ct * 2;
            float b2x = g_b2[n], b2y = g_b2[n + 1];
            float2 v0, v1;
            v0.x = (2.0f * acc[f][j][0] - z2a - b2x) * prec;
            v0.y = (2.0f * acc[f][j][1] - z2a - b2y) * prec;
            v1.x = (2.0f * acc[f][j][2] - z2b - b2x) * prec;
            v1.y = (2.0f * acc[f][j][3] - z2b - b2y) * prec;
            *(float2*)(g_scratch + (size_t)m * KS_ + n)       = v0;
            *(float2*)(g_scratch + (size_t)(m + 8) * KS_ + n) = v1;
        }
    }
}

// ============ GEMM2 (tf32 TC): zq = W @ books ==================================
#define PB2 130  /* pitch in float2 */
__global__ __launch_bounds__(256, 2)
void k_gemm2_tc(float* __restrict__ zq) {
    __shared__ float2 As[2][128 * P1];
    __shared__ float2 Bs2[2][8 * PB2];
    const int t = threadIdx.x;
    const int m0 = blockIdx.y * 128, n0 = blockIdx.x * 128;
    const int wid = t >> 5, lane = t & 31;
    const int wm = wid & 1, wn = wid >> 1;
    const int gr = lane >> 2, ct = lane & 3;

    float acc[4][4][4] = {};

    auto issue = [&](int kt, int st) {
#pragma unroll
        for (int i = 0; i < 2; i++) {
            int c = t + i * 256;
            {   // A: 128 rows x 4 chunks
                int row = c >> 2;
                int k2  = (c & 3) << 1;
                cp16(&As[st][row * P1 + k2],
                     g_wS + (size_t)(m0 + row) * KS_ + kt * 8 + k2);
            }
            {   // B: 8 rows x 64 chunks (128 float2 per row)
                int row = c >> 6;
                int n2  = (c & 63) << 1;
                cp16(&Bs2[st][row * PB2 + n2],
                     g_bkS + (size_t)(kt * 8 + row) * D_ + n0 + n2);
            }
        }
        CP_COMMIT;
    };

    const int T = KS_ / 8;       // 1024
    issue(0, 0);
    issue(1, 1);
    for (int kt = 0; kt < T; kt++) {
        if (kt + 1 < T) { CP_WAIT1; } else { CP_WAIT0; }
        __syncthreads();
        const int st = kt & 1;
        uint32_t ah[4][4], al[4][4], bh[4][2], bl[4][2];
#pragma unroll
        for (int f = 0; f < 4; f++) {
            int r = wm * 64 + f * 16 + gr;
            float2 v;
            v = As[st][r * P1 + ct];           ah[f][0] = __float_as_uint(v.x); al[f][0] = __float_as_uint(v.y);
            v = As[st][(r + 8) * P1 + ct];     ah[f][1] = __float_as_uint(v.x); al[f][1] = __float_as_uint(v.y);
            v = As[st][r * P1 + ct + 4];       ah[f][2] = __float_as_uint(v.x); al[f][2] = __float_as_uint(v.y);
            v = As[st][(r + 8) * P1 + ct + 4]; ah[f][3] = __float_as_uint(v.x); al[f][3] = __float_as_uint(v.y);
        }
#pragma unroll
        for (int j = 0; j < 4; j++) {
            int n = wn * 32 + j * 8 + gr;
            float2 v;
            v = Bs2[st][ct * PB2 + n];         bh[j][0] = __float_as_uint(v.x); bl[j][0] = __float_as_uint(v.y);
            v = Bs2[st][(ct + 4) * PB2 + n];   bh[j][1] = __float_as_uint(v.x); bl[j][1] = __float_as_uint(v.y);
        }
#pragma unroll
        for (int f = 0; f < 4; f++)
#pragma unroll
            for (int j = 0; j < 4; j++) {
                mma_tf32(acc[f][j], ah[f], bh[j]);
                mma_tf32(acc[f][j], ah[f], bl[j]);
                mma_tf32(acc[f][j], al[f], bh[j]);
            }
        __syncthreads();
        if (kt + 2 < T) issue(kt + 2, st);
    }

#pragma unroll
    for (int f = 0; f < 4; f++) {
        int m = m0 + wm * 64 + f * 16 + gr;
#pragma unroll
        for (int j = 0; j < 4; j++) {
            int n = n0 + wn * 32 + j * 8 + ct * 2;
            *(float2*)(zq + (size_t)m * D_ + n)       = make_float2(acc[f][j][0], acc[f][j][1]);
            *(float2*)(zq + (size_t)(m + 8) * D_ + n) = make_float2(acc[f][j][2], acc[f][j][3]);
        }
    }
}

// ---------------- softmax / gumbel / W / prob / log_prob -----------------------
__device__ __forceinline__ float block_reduce1(float a, float* red, int t, int is_sum) {
#pragma unroll
    for (int o = 16; o; o >>= 1) {
        float a2 = __shfl_xor_sync(0xffffffffu, a, o);
        a = is_sum ? (a + a2) : fmaxf(a, a2);
    }
    __syncthreads();
    if ((t & 31) == 0) red[t >> 5] = a;
    __syncthreads();
    float r = red[0];
#pragma unroll
    for (int w = 1; w < 8; w++) r = is_sum ? (r + red[w]) : fmaxf(r, red[w]);
    return r;
}

__global__ __launch_bounds__(256)
void k_soft(float* __restrict__ prob, float* __restrict__ logp,
            uint32_t k0, uint32_t k1) {
    __shared__ float red[8];
    int n = blockIdx.x;
    int b = blockIdx.y;
    int t = threadIdx.x;
    size_t row = (size_t)b * N_ + n;

    float wla = 0.f, wlb = 0.f;

    for (int k = 0; k < K_; k++) {
        float cp = g_cprobs[b * K_ + k];
        size_t base = (row * K_ + k) * (size_t)S_;

        float la = g_scratch[base + t];
        float lb = g_scratch[base + t + 256];

        uint32_t ia = (uint32_t)base + (uint32_t)t;
        float ga = gumbel_of(bits_to_unit(d_bits32(k0, k1, ia)));
        float gb = gumbel_of(bits_to_unit(d_bits32(k0, k1, ia + 256u)));
        float ya = (la + ga) * 2.0f;
        float yb = (lb + gb) * 2.0f;

        wla += cp * la; wlb += cp * lb;

        float M = block_reduce1(fmaxf(ya, yb), red, t, 0);
        float va = __expf(ya - M), vb = __expf(yb - M);
        float Z = block_reduce1(va + vb, red, t, 1);

        float f = cp / Z;
        g_wS[base + t]       = split2(va * f);
        g_wS[base + t + 256] = split2(vb * f);
    }

    float M = block_reduce1(fmaxf(wla, wlb), red, t, 0);
    float ea = __expf(wla - M), eb = __expf(wlb - M);
    float Z = block_reduce1(ea + eb, red, t, 1);
    float lz = logf(Z);

    size_t p0 = row * S_;
    prob[p0 + t]       = ea / Z;
    prob[p0 + t + 256] = eb / Z;
    logp[p0 + t]       = (wla - M) - lz;
    logp[p0 + t + 256] = (wlb - M) - lz;
}

// ---------------- host-side threefry --------------------------------------------
static void h_tf(uint32_t k0, uint32_t k1, uint32_t x0, uint32_t x1,
                 uint32_t* o0, uint32_t* o1) {
    uint32_t ks2 = k0 ^ k1 ^ 0x1BD11BDAu;
    x0 += k0; x1 += k1;
    const int ra[4] = {13, 15, 26, 6}, rb[4] = {17, 29, 16, 24};
#define HR(r) { x0 += x1; x1 = (x1 << (r)) | (x1 >> (32 - (r))); x1 ^= x0; }
    for (int i = 0; i < 4; i++) HR(ra[i]); x0 += k1;  x1 += ks2 + 1u;
    for (int i = 0; i < 4; i++) HR(rb[i]); x0 += ks2; x1 += k0  + 2u;
    for (int i = 0; i < 4; i++) HR(ra[i]); x0 += k0;  x1 += k1  + 3u;
    for (int i = 0; i < 4; i++) HR(rb[i]); x0 += k1;  x1 += ks2 + 4u;
    for (int i = 0; i < 4; i++) HR(ra[i]); x0 += ks2; x1 += k0  + 5u;
#undef HR
    *o0 = x0; *o1 = x1;
}

extern "C" void kernel_launch(void* const* d_in, const int* in_sizes, int n_in,
                              void* d_out, int out_size) {
    const float* ze       = (const float*)d_in[0];
    const float* c_logits = (const float*)d_in[1];
    const float* books    = (const float*)d_in[2];
    const float* lpq      = (const float*)d_in[3];
    const float* lpqc     = (const float*)d_in[4];

    float* out     = (float*)d_out;
    float* zq      = out;
    float* pscalar = out + ZQ_SIZE;
    float* prob    = pscalar + 1;
    float* logp    = prob + PROB_SIZE;

    uint32_t kg1_0, kg1_1, kg2_0, kg2_1;
    h_tf(0u, 42u, 0u, 0u, &kg1_0, &kg1_1);
    h_tf(0u, 42u, 0u, 1u, &kg2_0, &kg2_1);

    k_scalars<<<1, 1>>>(lpq, lpqc, pscalar);
    k_cprobs<<<1, 256>>>(c_logits, kg1_0, kg1_1);
    k_norms<<<96, 256>>>(ze, books);
    k_split<<<2048, 256>>>(ze, books);
    k_gemm1_tc<<<dim3(KS_ / 128, M_TOT / 128), 256>>>();
    k_soft<<<dim3(N_, B_), 256>>>(prob, logp, kg2_0, kg2_1);
    k_gemm2_tc<<<dim3(D_ / 128, M_TOT / 128), 256>>>(zq);
}

// round 8
// speedup vs baseline: 1.7097x; 1.7097x over previous
#include <cuda_runtime.h>
#include <cuda_bf16.h>
#include <cstdint>
#include <cstddef>

#define B_    16
#define N_    1024
#define D_    256
#define K_    16
#define S_    512
#define M_TOT (B_*N_)          /* 16384 */
#define KS_   (K_*S_)          /* 8192  */
#define ZQ_SIZE   (M_TOT*D_)   /* 4194304 */
#define PROB_SIZE ((size_t)M_TOT*S_) /* 8388608 */

typedef __nv_bfloat16 bf16;

// ---------------- scratch ------------------------------------------------------
__device__ float g_scratch[(size_t)M_TOT * KS_];   // logits fp32 (512 MB)
__device__ bf16  g_w0[(size_t)M_TOT * KS_];        // W hi plane (256 MB)
__device__ bf16  g_w1[(size_t)M_TOT * KS_];        // W lo plane (256 MB)
__device__ bf16  g_ze0[M_TOT * D_], g_ze1[M_TOT * D_];
__device__ bf16  g_bk0[KS_ * D_],  g_bk1[KS_ * D_];     // books [ks][d]
__device__ bf16  g_bkT0[D_ * KS_], g_bkT1[D_ * KS_];    // books [d][ks]
__device__ float g_z2[M_TOT];
__device__ float g_b2[KS_];
__device__ float g_cprobs[B_ * K_];
__device__ float g_prec[2];

// ---------------- threefry2x32-20 (JAX partitionable) --------------------------
__device__ __forceinline__ void d_tf(uint32_t k0, uint32_t k1,
                                     uint32_t x0, uint32_t x1,
                                     uint32_t& o0, uint32_t& o1) {
    uint32_t ks2 = k0 ^ k1 ^ 0x1BD11BDAu;
    x0 += k0; x1 += k1;
#define TFR(r) { x0 += x1; x1 = __funnelshift_l(x1, x1, r); x1 ^= x0; }
    TFR(13) TFR(15) TFR(26) TFR(6)   x0 += k1;  x1 += ks2 + 1u;
    TFR(17) TFR(29) TFR(16) TFR(24)  x0 += ks2; x1 += k0  + 2u;
    TFR(13) TFR(15) TFR(26) TFR(6)   x0 += k0;  x1 += k1  + 3u;
    TFR(17) TFR(29) TFR(16) TFR(24)  x0 += k1;  x1 += ks2 + 4u;
    TFR(13) TFR(15) TFR(26) TFR(6)   x0 += ks2; x1 += k0  + 5u;
#undef TFR
    o0 = x0; o1 = x1;
}

__device__ __forceinline__ uint32_t d_bits32(uint32_t k0, uint32_t k1, uint32_t i) {
    uint32_t o0, o1;
    d_tf(k0, k1, 0u, i, o0, o1);
    return o0 ^ o1;
}

__device__ __forceinline__ float bits_to_unit(uint32_t b) {
    return fmaxf(0.0f, __uint_as_float((b >> 9) | 0x3f800000u) - 1.0f);
}
__device__ __forceinline__ float gumbel_of(float u) {
    return -__logf(-__logf(u + 1e-10f) + 1e-10f);
}

// ---------------- bf16 mma helpers ----------------------------------------------
__device__ __forceinline__ void mma_bf16(float* c, const uint32_t* a, const uint32_t* b) {
    asm volatile(
        "mma.sync.aligned.m16n8k16.row.col.f32.bf16.bf16.f32 "
        "{%0,%1,%2,%3}, {%4,%5,%6,%7}, {%8,%9}, {%0,%1,%2,%3};"
        : "+f"(c[0]), "+f"(c[1]), "+f"(c[2]), "+f"(c[3])
        : "r"(a[0]), "r"(a[1]), "r"(a[2]), "r"(a[3]), "r"(b[0]), "r"(b[1]));
}

__device__ __forceinline__ void cp16(void* smem, const void* gmem) {
    unsigned s = (unsigned)__cvta_generic_to_shared(smem);
    asm volatile("cp.async.cg.shared.global [%0], [%1], 16;" :: "r"(s), "l"(gmem));
}
#define CP_COMMIT asm volatile("cp.async.commit_group;")
#define CP_WAIT1  asm volatile("cp.async.wait_group 1;")
#define CP_WAIT0  asm volatile("cp.async.wait_group 0;")

__device__ __forceinline__ uint32_t lds32(const bf16* p) {
    return *(const uint32_t*)p;
}

// ---------------- tiny kernels ---------------------------------------------------
__global__ void k_scalars(const float* __restrict__ lpq,
                          const float* __restrict__ lpqc,
                          float* __restrict__ out_scalar) {
    float pq   = 1.0f + expf(lpq[0]);
    float prec = 0.5f / fmaxf(pq, 1e-10f);
    float pqc  = 1.0f + expf(lpqc[0]);
    float precc= 0.5f / fmaxf(pqc, 1e-10f);
    g_prec[0] = prec;
    g_prec[1] = precc;
    out_scalar[0] = prec;
}

__global__ void k_cprobs(const float* __restrict__ c_logits,
                         uint32_t k0, uint32_t k1) {
    __shared__ float lg[256];
    int t = threadIdx.x;
    float u = bits_to_unit(d_bits32(k0, k1, (uint32_t)t));
    float pqc = g_prec[1];
    lg[t] = (c_logits[t] * pqc + gumbel_of(u)) * 2.0f;
    __syncthreads();
    if (t < 16) {
        float mx = -1e30f;
        for (int j = 0; j < 16; j++) mx = fmaxf(mx, lg[t * 16 + j]);
        float e[16], sm = 0.0f;
        for (int j = 0; j < 16; j++) { e[j] = expf(lg[t * 16 + j] - mx); sm += e[j]; }
        for (int j = 0; j < 16; j++) g_cprobs[t * 16 + j] = e[j] / sm;
    }
}

__global__ void k_norms(const float* __restrict__ ze,
                        const float* __restrict__ books) {
    int warps = (gridDim.x * blockDim.x) >> 5;
    int w     = (blockIdx.x * blockDim.x + threadIdx.x) >> 5;
    int lane  = threadIdx.x & 31;
    for (int r = w; r < M_TOT + KS_; r += warps) {
        const float4* p = (r < M_TOT)
            ? (const float4*)(ze + (size_t)r * D_)
            : (const float4*)(books + (size_t)(r - M_TOT) * D_);
        float s = 0.0f;
#pragma unroll
        for (int j = 0; j < 2; j++) {
            float4 v = p[lane + j * 32];
            s += v.x * v.x + v.y * v.y + v.z * v.z + v.w * v.w;
        }
#pragma unroll
        for (int o = 16; o; o >>= 1) s += __shfl_xor_sync(0xffffffffu, s, o);
        if (lane == 0) { if (r < M_TOT) g_z2[r] = s; else g_b2[r - M_TOT] = s; }
    }
}

// split ze/books into bf16 hi/lo planes (+ transposed books planes)
__global__ void k_split(const float* __restrict__ ze,
                        const float* __restrict__ books) {
    const int MZ = M_TOT * D_;
    const int BK = KS_ * D_;
    int stride = gridDim.x * blockDim.x;
    for (int i = blockIdx.x * blockDim.x + threadIdx.x; i < MZ; i += stride) {
        float v = ze[i];
        bf16 hi = __float2bfloat16(v);
        g_ze0[i] = hi;
        g_ze1[i] = __float2bfloat16(v - __bfloat162float(hi));
    }
    for (int i = blockIdx.x * blockDim.x + threadIdx.x; i < BK; i += stride) {
        float v = books[i];
        bf16 hi = __float2bfloat16(v);
        g_bk0[i] = hi;
        g_bk1[i] = __float2bfloat16(v - __bfloat162float(hi));
    }
    // transposed planes: j = d*KS_ + k  (coalesced writes, strided L2 reads)
    for (int j = blockIdx.x * blockDim.x + threadIdx.x; j < BK; j += stride) {
        int d = j / KS_, k = j - d * KS_;
        float v = books[(size_t)k * D_ + d];
        bf16 hi = __float2bfloat16(v);
        g_bkT0[j] = hi;
        g_bkT1[j] = __float2bfloat16(v - __bfloat162float(hi));
    }
}

// ============ GEMM1 (bf16x2 TC): scratch = (2*ze.booksT - z2 - b2)*prec ========
#define PAD 24   /* bf16 pitch: 16 data + 8 pad = 48B rows, conflict-free */
__global__ __launch_bounds__(256)
void k_gemm1_bf(void) {
    __shared__ bf16 sA[2][2][128 * PAD];
    __shared__ bf16 sB[2][2][128 * PAD];
    const int t = threadIdx.x;
    const int m0 = blockIdx.y * 128, n0 = blockIdx.x * 128;
    const int wid = t >> 5, lane = t & 31;
    const int wm = wid & 1, wn = wid >> 1;          // 2 x 4 warp grid
    const int gr = lane >> 2, ct = lane & 3;

    float acc[4][4][4] = {};

    auto issue = [&](int kt, int st) {
#pragma unroll
        for (int i = 0; i < 4; i++) {
            int c   = t + i * 256;          // 1024 chunks
            int ab  = c >> 9;
            int pl  = (c >> 8) & 1;
            int row = (c >> 1) & 127;
            int ch  = c & 1;
            if (ab == 0) {
                const bf16* src = (pl ? g_ze1 : g_ze0) + (size_t)(m0 + row) * D_ + kt * 16 + ch * 8;
                cp16(&sA[st][pl][row * PAD + ch * 8], src);
            } else {
                const bf16* src = (pl ? g_bk1 : g_bk0) + (size_t)(n0 + row) * D_ + kt * 16 + ch * 8;
                cp16(&sB[st][pl][row * PAD + ch * 8], src);
            }
        }
        CP_COMMIT;
    };

    const int T = D_ / 16;        // 16
    issue(0, 0);
    issue(1, 1);
    for (int kt = 0; kt < T; kt++) {
        if (kt + 1 < T) { CP_WAIT1; } else { CP_WAIT0; }
        __syncthreads();
        const int st = kt & 1;
        uint32_t a0[4][4], a1[4][4], b0[4][2], b1[4][2];
#pragma unroll
        for (int f = 0; f < 4; f++) {
            int r = wm * 64 + f * 16 + gr;
            a0[f][0] = lds32(&sA[st][0][r * PAD + 2 * ct]);
            a0[f][1] = lds32(&sA[st][0][(r + 8) * PAD + 2 * ct]);
            a0[f][2] = lds32(&sA[st][0][r * PAD + 2 * ct + 8]);
            a0[f][3] = lds32(&sA[st][0][(r + 8) * PAD + 2 * ct + 8]);
            a1[f][0] = lds32(&sA[st][1][r * PAD + 2 * ct]);
            a1[f][1] = lds32(&sA[st][1][(r + 8) * PAD + 2 * ct]);
            a1[f][2] = lds32(&sA[st][1][r * PAD + 2 * ct + 8]);
            a1[f][3] = lds32(&sA[st][1][(r + 8) * PAD + 2 * ct + 8]);
        }
#pragma unroll
        for (int j = 0; j < 4; j++) {
            int n = wn * 32 + j * 8 + gr;
            b0[j][0] = lds32(&sB[st][0][n * PAD + 2 * ct]);
            b0[j][1] = lds32(&sB[st][0][n * PAD + 2 * ct + 8]);
            b1[j][0] = lds32(&sB[st][1][n * PAD + 2 * ct]);
            b1[j][1] = lds32(&sB[st][1][n * PAD + 2 * ct + 8]);
        }
#pragma unroll
        for (int f = 0; f < 4; f++)
#pragma unroll
            for (int j = 0; j < 4; j++) {
                mma_bf16(acc[f][j], a0[f], b0[j]);
                mma_bf16(acc[f][j], a0[f], b1[j]);
                mma_bf16(acc[f][j], a1[f], b0[j]);
                mma_bf16(acc[f][j], a1[f], b1[j]);
            }
        __syncthreads();
        if (kt + 2 < T) issue(kt + 2, st);
    }

    const float prec = g_prec[0];
#pragma unroll
    for (int f = 0; f < 4; f++) {
        int m = m0 + wm * 64 + f * 16 + gr;
        float z2a = g_z2[m], z2b = g_z2[m + 8];
#pragma unroll
        for (int j = 0; j < 4; j++) {
            int n = n0 + wn * 32 + j * 8 + ct * 2;
            float b2x = g_b2[n], b2y = g_b2[n + 1];
            float2 v0, v1;
            v0.x = (2.0f * acc[f][j][0] - z2a - b2x) * prec;
            v0.y = (2.0f * acc[f][j][1] - z2a - b2y) * prec;
            v1.x = (2.0f * acc[f][j][2] - z2b - b2x) * prec;
            v1.y = (2.0f * acc[f][j][3] - z2b - b2y) * prec;
            *(float2*)(g_scratch + (size_t)m * KS_ + n)       = v0;
            *(float2*)(g_scratch + (size_t)(m + 8) * KS_ + n) = v1;
        }
    }
}

// ============ GEMM2 (bf16x2 TC, 3-term): zq = W @ books ========================
__global__ __launch_bounds__(256)
void k_gemm2_bf(float* __restrict__ zq) {
    __shared__ bf16 sA[2][2][128 * PAD];
    __shared__ bf16 sB[2][2][128 * PAD];
    const int t = threadIdx.x;
    const int m0 = blockIdx.y * 128, n0 = blockIdx.x * 128;
    const int wid = t >> 5, lane = t & 31;
    const int wm = wid & 1, wn = wid >> 1;
    const int gr = lane >> 2, ct = lane & 3;

    float acc[4][4][4] = {};

    auto issue = [&](int kt, int st) {
#pragma unroll
        for (int i = 0; i < 4; i++) {
            int c   = t + i * 256;
            int ab  = c >> 9;
            int pl  = (c >> 8) & 1;
            int row = (c >> 1) & 127;
            int ch  = c & 1;
            if (ab == 0) {
                const bf16* src = (pl ? g_w1 : g_w0) + (size_t)(m0 + row) * KS_ + kt * 16 + ch * 8;
                cp16(&sA[st][pl][row * PAD + ch * 8], src);
            } else {
                const bf16* src = (pl ? g_bkT1 : g_bkT0) + (size_t)(n0 + row) * KS_ + kt * 16 + ch * 8;
                cp16(&sB[st][pl][row * PAD + ch * 8], src);
            }
        }
        CP_COMMIT;
    };

    const int T = KS_ / 16;       // 512
    issue(0, 0);
    issue(1, 1);
    for (int kt = 0; kt < T; kt++) {
        if (kt + 1 < T) { CP_WAIT1; } else { CP_WAIT0; }
        __syncthreads();
        const int st = kt & 1;
        uint32_t a0[4][4], a1[4][4], b0[4][2], b1[4][2];
#pragma unroll
        for (int f = 0; f < 4; f++) {
            int r = wm * 64 + f * 16 + gr;
            a0[f][0] = lds32(&sA[st][0][r * PAD + 2 * ct]);
            a0[f][1] = lds32(&sA[st][0][(r + 8) * PAD + 2 * ct]);
            a0[f][2] = lds32(&sA[st][0][r * PAD + 2 * ct + 8]);
            a0[f][3] = lds32(&sA[st][0][(r + 8) * PAD + 2 * ct + 8]);
            a1[f][0] = lds32(&sA[st][1][r * PAD + 2 * ct]);
            a1[f][1] = lds32(&sA[st][1][(r + 8) * PAD + 2 * ct]);
            a1[f][2] = lds32(&sA[st][1][r * PAD + 2 * ct + 8]);
            a1[f][3] = lds32(&sA[st][1][(r + 8) * PAD + 2 * ct + 8]);
        }
#pragma unroll
        for (int j = 0; j < 4; j++) {
            int n = wn * 32 + j * 8 + gr;
            b0[j][0] = lds32(&sB[st][0][n * PAD + 2 * ct]);
            b0[j][1] = lds32(&sB[st][0][n * PAD + 2 * ct + 8]);
            b1[j][0] = lds32(&sB[st][1][n * PAD + 2 * ct]);
            b1[j][1] = lds32(&sB[st][1][n * PAD + 2 * ct + 8]);
        }
#pragma unroll
        for (int f = 0; f < 4; f++)
#pragma unroll
            for (int j = 0; j < 4; j++) {
                mma_bf16(acc[f][j], a0[f], b0[j]);
                mma_bf16(acc[f][j], a0[f], b1[j]);
                mma_bf16(acc[f][j], a1[f], b0[j]);
            }
        __syncthreads();
        if (kt + 2 < T) issue(kt + 2, st);
    }

#pragma unroll
    for (int f = 0; f < 4; f++) {
        int m = m0 + wm * 64 + f * 16 + gr;
#pragma unroll
        for (int j = 0; j < 4; j++) {
            int n = n0 + wn * 32 + j * 8 + ct * 2;
            *(float2*)(zq + (size_t)m * D_ + n)       = make_float2(acc[f][j][0], acc[f][j][1]);
            *(float2*)(zq + (size_t)(m + 8) * D_ + n) = make_float2(acc[f][j][2], acc[f][j][3]);
        }
    }
}

// ---------------- softmax / gumbel / W / prob / log_prob -----------------------
__device__ __forceinline__ float block_reduce1(float a, float* red, int t, int is_sum) {
#pragma unroll
    for (int o = 16; o; o >>= 1) {
        float a2 = __shfl_xor_sync(0xffffffffu, a, o);
        a = is_sum ? (a + a2) : fmaxf(a, a2);
    }
    __syncthreads();
    if ((t & 31) == 0) red[t >> 5] = a;
    __syncthreads();
    float r = red[0];
#pragma unroll
    for (int w = 1; w < 8; w++) r = is_sum ? (r + red[w]) : fmaxf(r, red[w]);
    return r;
}

__global__ __launch_bounds__(256)
void k_soft(float* __restrict__ prob, float* __restrict__ logp,
            uint32_t k0, uint32_t k1) {
    __shared__ float red[8];
    int n = blockIdx.x;
    int b = blockIdx.y;
    int t = threadIdx.x;
    size_t row = (size_t)b * N_ + n;

    float wla = 0.f, wlb = 0.f;

    for (int k = 0; k < K_; k++) {
        float cp = g_cprobs[b * K_ + k];
        size_t base = (row * K_ + k) * (size_t)S_;

        float la = g_scratch[base + t];
        float lb = g_scratch[base + t + 256];

        uint32_t ia = (uint32_t)base + (uint32_t)t;
        float ga = gumbel_of(bits_to_unit(d_bits32(k0, k1, ia)));
        float gb = gumbel_of(bits_to_unit(d_bits32(k0, k1, ia + 256u)));
        float ya = (la + ga) * 2.0f;
        float yb = (lb + gb) * 2.0f;

        wla += cp * la; wlb += cp * lb;

        float M = block_reduce1(fmaxf(ya, yb), red, t, 0);
        float va = __expf(ya - M), vb = __expf(yb - M);
        float Z = block_reduce1(va + vb, red, t, 1);

        float f = cp / Z;
        float w0 = va * f, w1 = vb * f;
        bf16 h0 = __float2bfloat16(w0);
        bf16 h1 = __float2bfloat16(w1);
        g_w0[base + t]       = h0;
        g_w1[base + t]       = __float2bfloat16(w0 - __bfloat162float(h0));
        g_w0[base + t + 256] = h1;
        g_w1[base + t + 256] = __float2bfloat16(w1 - __bfloat162float(h1));
    }

    float M = block_reduce1(fmaxf(wla, wlb), red, t, 0);
    float ea = __expf(wla - M), eb = __expf(wlb - M);
    float Z = block_reduce1(ea + eb, red, t, 1);
    float lz = __logf(Z);

    size_t p0 = row * S_;
    prob[p0 + t]       = ea / Z;
    prob[p0 + t + 256] = eb / Z;
    logp[p0 + t]       = (wla - M) - lz;
    logp[p0 + t + 256] = (wlb - M) - lz;
}

// ---------------- host-side threefry --------------------------------------------
static void h_tf(uint32_t k0, uint32_t k1, uint32_t x0, uint32_t x1,
                 uint32_t* o0, uint32_t* o1) {
    uint32_t ks2 = k0 ^ k1 ^ 0x1BD11BDAu;
    x0 += k0; x1 += k1;
    const int ra[4] = {13, 15, 26, 6}, rb[4] = {17, 29, 16, 24};
#define HR(r) { x0 += x1; x1 = (x1 << (r)) | (x1 >> (32 - (r))); x1 ^= x0; }
    for (int i = 0; i < 4; i++) HR(ra[i]); x0 += k1;  x1 += ks2 + 1u;
    for (int i = 0; i < 4; i++) HR(rb[i]); x0 += ks2; x1 += k0  + 2u;
    for (int i = 0; i < 4; i++) HR(ra[i]); x0 += k0;  x1 += k1  + 3u;
    for (int i = 0; i < 4; i++) HR(rb[i]); x0 += k1;  x1 += ks2 + 4u;
    for (int i = 0; i < 4; i++) HR(ra[i]); x0 += ks2; x1 += k0  + 5u;
#undef HR
    *o0 = x0; *o1 = x1;
}

extern "C" void kernel_launch(void* const* d_in, const int* in_sizes, int n_in,
                              void* d_out, int out_size) {
    const float* ze       = (const float*)d_in[0];
    const float* c_logits = (const float*)d_in[1];
    const float* books    = (const float*)d_in[2];
    const float* lpq      = (const float*)d_in[3];
    const float* lpqc     = (const float*)d_in[4];

    float* out     = (float*)d_out;
    float* zq      = out;
    float* pscalar = out + ZQ_SIZE;
    float* prob    = pscalar + 1;
    float* logp    = prob + PROB_SIZE;

    uint32_t kg1_0, kg1_1, kg2_0, kg2_1;
    h_tf(0u, 42u, 0u, 0u, &kg1_0, &kg1_1);
    h_tf(0u, 42u, 0u, 1u, &kg2_0, &kg2_1);

    k_scalars<<<1, 1>>>(lpq, lpqc, pscalar);
    k_cprobs<<<1, 256>>>(c_logits, kg1_0, kg1_1);
    k_norms<<<96, 256>>>(ze, books);
    k_split<<<1024, 256>>>(ze, books);
    k_gemm1_bf<<<dim3(KS_ / 128, M_TOT / 128), 256>>>();
    k_soft<<<dim3(N_, B_), 256>>>(prob, logp, kg2_0, kg2_1);
    k_gemm2_bf<<<dim3(D_ / 128, M_TOT / 128), 256>>>(zq);
}

// round 9
// speedup vs baseline: 1.8447x; 1.0790x over previous
#include <cuda_runtime.h>
#include <cuda_bf16.h>
#include <cstdint>
#include <cstddef>

#define B_    16
#define N_    1024
#define D_    256
#define K_    16
#define S_    512
#define M_TOT (B_*N_)          /* 16384 */
#define KS_   (K_*S_)          /* 8192  */
#define ZQ_SIZE   (M_TOT*D_)   /* 4194304 */
#define PROB_SIZE ((size_t)M_TOT*S_) /* 8388608 */

typedef __nv_bfloat16 bf16;

// ---------------- scratch ------------------------------------------------------
__device__ float g_scratch[(size_t)M_TOT * KS_];   // logits fp32 (512 MB)
__device__ bf16  g_w0[(size_t)M_TOT * KS_];        // W hi plane (256 MB)
__device__ bf16  g_w1[(size_t)M_TOT * KS_];        // W lo plane (256 MB)
__device__ bf16  g_ze0[M_TOT * D_], g_ze1[M_TOT * D_];
__device__ bf16  g_bk0[KS_ * D_],  g_bk1[KS_ * D_];     // books [ks][d]
__device__ bf16  g_bkT0[D_ * KS_], g_bkT1[D_ * KS_];    // books [d][ks]
__device__ float g_z2[M_TOT];
__device__ float g_b2[KS_];
__device__ float g_cprobs[B_ * K_];
__device__ float g_prec[2];

// ---------------- threefry2x32-20 (JAX partitionable) --------------------------
__device__ __forceinline__ void d_tf(uint32_t k0, uint32_t k1,
                                     uint32_t x0, uint32_t x1,
                                     uint32_t& o0, uint32_t& o1) {
    uint32_t ks2 = k0 ^ k1 ^ 0x1BD11BDAu;
    x0 += k0; x1 += k1;
#define TFR(r) { x0 += x1; x1 = __funnelshift_l(x1, x1, r); x1 ^= x0; }
    TFR(13) TFR(15) TFR(26) TFR(6)   x0 += k1;  x1 += ks2 + 1u;
    TFR(17) TFR(29) TFR(16) TFR(24)  x0 += ks2; x1 += k0  + 2u;
    TFR(13) TFR(15) TFR(26) TFR(6)   x0 += k0;  x1 += k1  + 3u;
    TFR(17) TFR(29) TFR(16) TFR(24)  x0 += k1;  x1 += ks2 + 4u;
    TFR(13) TFR(15) TFR(26) TFR(6)   x0 += ks2; x1 += k0  + 5u;
#undef TFR
    o0 = x0; o1 = x1;
}

__device__ __forceinline__ uint32_t d_bits32(uint32_t k0, uint32_t k1, uint32_t i) {
    uint32_t o0, o1;
    d_tf(k0, k1, 0u, i, o0, o1);
    return o0 ^ o1;
}

__device__ __forceinline__ float bits_to_unit(uint32_t b) {
    return fmaxf(0.0f, __uint_as_float((b >> 9) | 0x3f800000u) - 1.0f);
}
__device__ __forceinline__ float gumbel_of(float u) {
    return -__logf(-__logf(u + 1e-10f) + 1e-10f);
}

// ---------------- bf16 mma helpers ----------------------------------------------
__device__ __forceinline__ void mma_bf16(float* c, const uint32_t* a, const uint32_t* b) {
    asm volatile(
        "mma.sync.aligned.m16n8k16.row.col.f32.bf16.bf16.f32 "
        "{%0,%1,%2,%3}, {%4,%5,%6,%7}, {%8,%9}, {%0,%1,%2,%3};"
        : "+f"(c[0]), "+f"(c[1]), "+f"(c[2]), "+f"(c[3])
        : "r"(a[0]), "r"(a[1]), "r"(a[2]), "r"(a[3]), "r"(b[0]), "r"(b[1]));
}

__device__ __forceinline__ void cp16(void* smem, const void* gmem) {
    unsigned s = (unsigned)__cvta_generic_to_shared(smem);
    asm volatile("cp.async.cg.shared.global [%0], [%1], 16;" :: "r"(s), "l"(gmem));
}
#define CP_COMMIT asm volatile("cp.async.commit_group;")
#define CP_WAIT1  asm volatile("cp.async.wait_group 1;")
#define CP_WAIT0  asm volatile("cp.async.wait_group 0;")

__device__ __forceinline__ uint32_t lds32(const bf16* p) {
    return *(const uint32_t*)p;
}

// ---------------- tiny kernels ---------------------------------------------------
__global__ void k_scalars(const float* __restrict__ lpq,
                          const float* __restrict__ lpqc,
                          float* __restrict__ out_scalar) {
    float pq   = 1.0f + expf(lpq[0]);
    float prec = 0.5f / fmaxf(pq, 1e-10f);
    float pqc  = 1.0f + expf(lpqc[0]);
    float precc= 0.5f / fmaxf(pqc, 1e-10f);
    g_prec[0] = prec;
    g_prec[1] = precc;
    out_scalar[0] = prec;
}

__global__ void k_cprobs(const float* __restrict__ c_logits,
                         uint32_t k0, uint32_t k1) {
    __shared__ float lg[256];
    int t = threadIdx.x;
    float u = bits_to_unit(d_bits32(k0, k1, (uint32_t)t));
    float pqc = g_prec[1];
    lg[t] = (c_logits[t] * pqc + gumbel_of(u)) * 2.0f;
    __syncthreads();
    if (t < 16) {
        float mx = -1e30f;
        for (int j = 0; j < 16; j++) mx = fmaxf(mx, lg[t * 16 + j]);
        float e[16], sm = 0.0f;
        for (int j = 0; j < 16; j++) { e[j] = expf(lg[t * 16 + j] - mx); sm += e[j]; }
        for (int j = 0; j < 16; j++) g_cprobs[t * 16 + j] = e[j] / sm;
    }
}

__global__ void k_norms(const float* __restrict__ ze,
                        const float* __restrict__ books) {
    int warps = (gridDim.x * blockDim.x) >> 5;
    int w     = (blockIdx.x * blockDim.x + threadIdx.x) >> 5;
    int lane  = threadIdx.x & 31;
    for (int r = w; r < M_TOT + KS_; r += warps) {
        const float4* p = (r < M_TOT)
            ? (const float4*)(ze + (size_t)r * D_)
            : (const float4*)(books + (size_t)(r - M_TOT) * D_);
        float s = 0.0f;
#pragma unroll
        for (int j = 0; j < 2; j++) {
            float4 v = p[lane + j * 32];
            s += v.x * v.x + v.y * v.y + v.z * v.z + v.w * v.w;
        }
#pragma unroll
        for (int o = 16; o; o >>= 1) s += __shfl_xor_sync(0xffffffffu, s, o);
        if (lane == 0) { if (r < M_TOT) g_z2[r] = s; else g_b2[r - M_TOT] = s; }
    }
}

// split ze/books into bf16 hi/lo planes (+ transposed books planes)
__global__ void k_split(const float* __restrict__ ze,
                        const float* __restrict__ books) {
    const int MZ = M_TOT * D_;
    const int BK = KS_ * D_;
    int stride = gridDim.x * blockDim.x;
    for (int i = blockIdx.x * blockDim.x + threadIdx.x; i < MZ; i += stride) {
        float v = ze[i];
        bf16 hi = __float2bfloat16(v);
        g_ze0[i] = hi;
        g_ze1[i] = __float2bfloat16(v - __bfloat162float(hi));
    }
    for (int i = blockIdx.x * blockDim.x + threadIdx.x; i < BK; i += stride) {
        float v = books[i];
        bf16 hi = __float2bfloat16(v);
        g_bk0[i] = hi;
        g_bk1[i] = __float2bfloat16(v - __bfloat162float(hi));
    }
    for (int j = blockIdx.x * blockDim.x + threadIdx.x; j < BK; j += stride) {
        int d = j / KS_, k = j - d * KS_;
        float v = books[(size_t)k * D_ + d];
        bf16 hi = __float2bfloat16(v);
        g_bkT0[j] = hi;
        g_bkT1[j] = __float2bfloat16(v - __bfloat162float(hi));
    }
}

// ============ GEMM1 (bf16x2 TC, 3-term): scratch = (2*ze.booksT - z2 - b2)*prec
#define PAD 24
__global__ __launch_bounds__(256)
void k_gemm1_bf(void) {
    __shared__ bf16 sA[2][2][128 * PAD];
    __shared__ bf16 sB[2][2][128 * PAD];
    const int t = threadIdx.x;
    const int m0 = blockIdx.y * 128, n0 = blockIdx.x * 128;
    const int wid = t >> 5, lane = t & 31;
    const int wm = wid & 1, wn = wid >> 1;
    const int gr = lane >> 2, ct = lane & 3;

    float acc[4][4][4] = {};

    auto issue = [&](int kt, int st) {
#pragma unroll
        for (int i = 0; i < 4; i++) {
            int c   = t + i * 256;
            int ab  = c >> 9;
            int pl  = (c >> 8) & 1;
            int row = (c >> 1) & 127;
            int ch  = c & 1;
            if (ab == 0) {
                const bf16* src = (pl ? g_ze1 : g_ze0) + (size_t)(m0 + row) * D_ + kt * 16 + ch * 8;
                cp16(&sA[st][pl][row * PAD + ch * 8], src);
            } else {
                const bf16* src = (pl ? g_bk1 : g_bk0) + (size_t)(n0 + row) * D_ + kt * 16 + ch * 8;
                cp16(&sB[st][pl][row * PAD + ch * 8], src);
            }
        }
        CP_COMMIT;
    };

    const int T = D_ / 16;
    issue(0, 0);
    issue(1, 1);
    for (int kt = 0; kt < T; kt++) {
        if (kt + 1 < T) { CP_WAIT1; } else { CP_WAIT0; }
        __syncthreads();
        const int st = kt & 1;
        uint32_t a0[4][4], a1[4][4], b0[4][2], b1[4][2];
#pragma unroll
        for (int f = 0; f < 4; f++) {
            int r = wm * 64 + f * 16 + gr;
            a0[f][0] = lds32(&sA[st][0][r * PAD + 2 * ct]);
            a0[f][1] = lds32(&sA[st][0][(r + 8) * PAD + 2 * ct]);
            a0[f][2] = lds32(&sA[st][0][r * PAD + 2 * ct + 8]);
            a0[f][3] = lds32(&sA[st][0][(r + 8) * PAD + 2 * ct + 8]);
            a1[f][0] = lds32(&sA[st][1][r * PAD + 2 * ct]);
            a1[f][1] = lds32(&sA[st][1][(r + 8) * PAD + 2 * ct]);
            a1[f][2] = lds32(&sA[st][1][r * PAD + 2 * ct + 8]);
            a1[f][3] = lds32(&sA[st][1][(r + 8) * PAD + 2 * ct + 8]);
        }
#pragma unroll
        for (int j = 0; j < 4; j++) {
            int n = wn * 32 + j * 8 + gr;
            b0[j][0] = lds32(&sB[st][0][n * PAD + 2 * ct]);
            b0[j][1] = lds32(&sB[st][0][n * PAD + 2 * ct + 8]);
            b1[j][0] = lds32(&sB[st][1][n * PAD + 2 * ct]);
            b1[j][1] = lds32(&sB[st][1][n * PAD + 2 * ct + 8]);
        }
#pragma unroll
        for (int f = 0; f < 4; f++)
#pragma unroll
            for (int j = 0; j < 4; j++) {
                mma_bf16(acc[f][j], a0[f], b0[j]);
                mma_bf16(acc[f][j], a0[f], b1[j]);
                mma_bf16(acc[f][j], a1[f], b0[j]);
            }
        __syncthreads();
        if (kt + 2 < T) issue(kt + 2, st);
    }

    const float prec = g_prec[0];
#pragma unroll
    for (int f = 0; f < 4; f++) {
        int m = m0 + wm * 64 + f * 16 + gr;
        float z2a = g_z2[m], z2b = g_z2[m + 8];
#pragma unroll
        for (int j = 0; j < 4; j++) {
            int n = n0 + wn * 32 + j * 8 + ct * 2;
            float b2x = g_b2[n], b2y = g_b2[n + 1];
            float2 v0, v1;
            v0.x = (2.0f * acc[f][j][0] - z2a - b2x) * prec;
            v0.y = (2.0f * acc[f][j][1] - z2a - b2y) * prec;
            v1.x = (2.0f * acc[f][j][2] - z2b - b2x) * prec;
            v1.y = (2.0f * acc[f][j][3] - z2b - b2y) * prec;
            *(float2*)(g_scratch + (size_t)m * KS_ + n)       = v0;
            *(float2*)(g_scratch + (size_t)(m + 8) * KS_ + n) = v1;
        }
    }
}

// ============ GEMM2 (bf16x2 TC, 3-term): zq = W @ books ========================
__global__ __launch_bounds__(256)
void k_gemm2_bf(float* __restrict__ zq) {
    __shared__ bf16 sA[2][2][128 * PAD];
    __shared__ bf16 sB[2][2][128 * PAD];
    const int t = threadIdx.x;
    const int m0 = blockIdx.y * 128, n0 = blockIdx.x * 128;
    const int wid = t >> 5, lane = t & 31;
    const int wm = wid & 1, wn = wid >> 1;
    const int gr = lane >> 2, ct = lane & 3;

    float acc[4][4][4] = {};

    auto issue = [&](int kt, int st) {
#pragma unroll
        for (int i = 0; i < 4; i++) {
            int c   = t + i * 256;
            int ab  = c >> 9;
            int pl  = (c >> 8) & 1;
            int row = (c >> 1) & 127;
            int ch  = c & 1;
            if (ab == 0) {
                const bf16* src = (pl ? g_w1 : g_w0) + (size_t)(m0 + row) * KS_ + kt * 16 + ch * 8;
                cp16(&sA[st][pl][row * PAD + ch * 8], src);
            } else {
                const bf16* src = (pl ? g_bkT1 : g_bkT0) + (size_t)(n0 + row) * KS_ + kt * 16 + ch * 8;
                cp16(&sB[st][pl][row * PAD + ch * 8], src);
            }
        }
        CP_COMMIT;
    };

    const int T = KS_ / 16;
    issue(0, 0);
    issue(1, 1);
    for (int kt = 0; kt < T; kt++) {
        if (kt + 1 < T) { CP_WAIT1; } else { CP_WAIT0; }
        __syncthreads();
        const int st = kt & 1;
        uint32_t a0[4][4], a1[4][4], b0[4][2], b1[4][2];
#pragma unroll
        for (int f = 0; f < 4; f++) {
            int r = wm * 64 + f * 16 + gr;
            a0[f][0] = lds32(&sA[st][0][r * PAD + 2 * ct]);
            a0[f][1] = lds32(&sA[st][0][(r + 8) * PAD + 2 * ct]);
            a0[f][2] = lds32(&sA[st][0][r * PAD + 2 * ct + 8]);
            a0[f][3] = lds32(&sA[st][0][(r + 8) * PAD + 2 * ct + 8]);
            a1[f][0] = lds32(&sA[st][1][r * PAD + 2 * ct]);
            a1[f][1] = lds32(&sA[st][1][(r + 8) * PAD + 2 * ct]);
            a1[f][2] = lds32(&sA[st][1][r * PAD + 2 * ct + 8]);
            a1[f][3] = lds32(&sA[st][1][(r + 8) * PAD + 2 * ct + 8]);
        }
#pragma unroll
        for (int j = 0; j < 4; j++) {
            int n = wn * 32 + j * 8 + gr;
            b0[j][0] = lds32(&sB[st][0][n * PAD + 2 * ct]);
            b0[j][1] = lds32(&sB[st][0][n * PAD + 2 * ct + 8]);
            b1[j][0] = lds32(&sB[st][1][n * PAD + 2 * ct]);
            b1[j][1] = lds32(&sB[st][1][n * PAD + 2 * ct + 8]);
        }
#pragma unroll
        for (int f = 0; f < 4; f++)
#pragma unroll
            for (int j = 0; j < 4; j++) {
                mma_bf16(acc[f][j], a0[f], b0[j]);
                mma_bf16(acc[f][j], a0[f], b1[j]);
                mma_bf16(acc[f][j], a1[f], b0[j]);
            }
        __syncthreads();
        if (kt + 2 < T) issue(kt + 2, st);
    }

#pragma unroll
    for (int f = 0; f < 4; f++) {
        int m = m0 + wm * 64 + f * 16 + gr;
#pragma unroll
        for (int j = 0; j < 4; j++) {
            int n = n0 + wn * 32 + j * 8 + ct * 2;
            *(float2*)(zq + (size_t)m * D_ + n)       = make_float2(acc[f][j][0], acc[f][j][1]);
            *(float2*)(zq + (size_t)(m + 8) * D_ + n) = make_float2(acc[f][j][2], acc[f][j][3]);
        }
    }
}

// ---------------- softmax / gumbel / W / prob / log_prob -----------------------
// warp-per-k version: each warp owns full S=512 rows -> warp-local softmax
__device__ __forceinline__ float block_reduce1(float a, float* red, int t, int is_sum) {
#pragma unroll
    for (int o = 16; o; o >>= 1) {
        float a2 = __shfl_xor_sync(0xffffffffu, a, o);
        a = is_sum ? (a + a2) : fmaxf(a, a2);
    }
    __syncthreads();
    if ((t & 31) == 0) red[t >> 5] = a;
    __syncthreads();
    float r = red[0];
#pragma unroll
    for (int w = 1; w < 8; w++) r = is_sum ? (r + red[w]) : fmaxf(r, red[w]);
    return r;
}

__global__ __launch_bounds__(256)
void k_soft(float* __restrict__ prob, float* __restrict__ logp,
            uint32_t k0, uint32_t k1) {
    __shared__ float s_wl[8][S_];
    __shared__ float red[8];
    const int n = blockIdx.x;
    const int b = blockIdx.y;
    const int t = threadIdx.x;
    const int w = t >> 5, lane = t & 31;
    const size_t row = (size_t)b * N_ + n;

    float wl[16];
#pragma unroll
    for (int i = 0; i < 16; i++) wl[i] = 0.0f;

#pragma unroll
    for (int it = 0; it < 2; it++) {
        const int k = it * 8 + w;
        const float cp = g_cprobs[b * K_ + k];
        const size_t base = (row * K_ + k) * (size_t)S_;

        float y[16];
        float mx = -1e30f;
#pragma unroll
        for (int j = 0; j < 4; j++) {
            int s4 = j * 128 + lane * 4;
            float4 lg = *(const float4*)(g_scratch + base + s4);
            uint32_t ia = (uint32_t)base + (uint32_t)s4;
#pragma unroll
            for (int e = 0; e < 4; e++) {
                float la = (&lg.x)[e];
                float g  = gumbel_of(bits_to_unit(d_bits32(k0, k1, ia + e)));
                float yy = (la + g) * 2.0f;
                y[j * 4 + e] = yy;
                wl[j * 4 + e] += cp * la;
                mx = fmaxf(mx, yy);
            }
        }
#pragma unroll
        for (int o = 16; o; o >>= 1) mx = fmaxf(mx, __shfl_xor_sync(0xffffffffu, mx, o));
        float sum = 0.0f;
#pragma unroll
        for (int i = 0; i < 16; i++) { y[i] = __expf(y[i] - mx); sum += y[i]; }
#pragma unroll
        for (int o = 16; o; o >>= 1) sum += __shfl_xor_sync(0xffffffffu, sum, o);
        const float f = cp / sum;
#pragma unroll
        for (int j = 0; j < 4; j++) {
            int s4 = j * 128 + lane * 4;
            uint32_t p0, p1_;   // packed hi plane (2+2 bf16)
            uint32_t q0, q1_;   // packed lo plane
            float v0 = y[j*4+0] * f, v1 = y[j*4+1] * f, v2 = y[j*4+2] * f, v3 = y[j*4+3] * f;
            bf16 h0 = __float2bfloat16(v0), h1 = __float2bfloat16(v1);
            bf16 h2 = __float2bfloat16(v2), h3 = __float2bfloat16(v3);
            bf16 l0 = __float2bfloat16(v0 - __bfloat162float(h0));
            bf16 l1 = __float2bfloat16(v1 - __bfloat162float(h1));
            bf16 l2 = __float2bfloat16(v2 - __bfloat162float(h2));
            bf16 l3 = __float2bfloat16(v3 - __bfloat162float(h3));
            p0  = (uint32_t)__bfloat16_as_ushort(h0) | ((uint32_t)__bfloat16_as_ushort(h1) << 16);
            p1_ = (uint32_t)__bfloat16_as_ushort(h2) | ((uint32_t)__bfloat16_as_ushort(h3) << 16);
            q0  = (uint32_t)__bfloat16_as_ushort(l0) | ((uint32_t)__bfloat16_as_ushort(l1) << 16);
            q1_ = (uint32_t)__bfloat16_as_ushort(l2) | ((uint32_t)__bfloat16_as_ushort(l3) << 16);
            *(uint2*)(g_w0 + base + s4) = make_uint2(p0, p1_);
            *(uint2*)(g_w1 + base + s4) = make_uint2(q0, q1_);
        }
    }

    // cross-warp reduce of weighted logits
#pragma unroll
    for (int j = 0; j < 4; j++) {
        int s4 = j * 128 + lane * 4;
        *(float4*)(&s_wl[w][s4]) = make_float4(wl[j*4+0], wl[j*4+1], wl[j*4+2], wl[j*4+3]);
    }
    __syncthreads();

    float wla = 0.f, wlb = 0.f;
#pragma unroll
    for (int w2 = 0; w2 < 8; w2++) { wla += s_wl[w2][t]; wlb += s_wl[w2][t + 256]; }

    float M = block_reduce1(fmaxf(wla, wlb), red, t, 0);
    float ea = __expf(wla - M), eb = __expf(wlb - M);
    float Z = block_reduce1(ea + eb, red, t, 1);
    float lz = __logf(Z);

    size_t p0 = row * S_;
    prob[p0 + t]       = ea / Z;
    prob[p0 + t + 256] = eb / Z;
    logp[p0 + t]       = (wla - M) - lz;
    logp[p0 + t + 256] = (wlb - M) - lz;
}

// ---------------- host-side threefry --------------------------------------------
static void h_tf(uint32_t k0, uint32_t k1, uint32_t x0, uint32_t x1,
                 uint32_t* o0, uint32_t* o1) {
    uint32_t ks2 = k0 ^ k1 ^ 0x1BD11BDAu;
    x0 += k0; x1 += k1;
    const int ra[4] = {13, 15, 26, 6}, rb[4] = {17, 29, 16, 24};
#define HR(r) { x0 += x1; x1 = (x1 << (r)) | (x1 >> (32 - (r))); x1 ^= x0; }
    for (int i = 0; i < 4; i++) HR(ra[i]); x0 += k1;  x1 += ks2 + 1u;
    for (int i = 0; i < 4; i++) HR(rb[i]); x0 += ks2; x1 += k0  + 2u;
    for (int i = 0; i < 4; i++) HR(ra[i]); x0 += k0;  x1 += k1  + 3u;
    for (int i = 0; i < 4; i++) HR(rb[i]); x0 += k1;  x1 += ks2 + 4u;
    for (int i = 0; i < 4; i++) HR(ra[i]); x0 += ks2; x1 += k0  + 5u;
#undef HR
    *o0 = x0; *o1 = x1;
}

extern "C" void kernel_launch(void* const* d_in, const int* in_sizes, int n_in,
                              void* d_out, int out_size) {
    const float* ze       = (const float*)d_in[0];
    const float* c_logits = (const float*)d_in[1];
    const float* books    = (const float*)d_in[2];
    const float* lpq      = (const float*)d_in[3];
    const float* lpqc     = (const float*)d_in[4];

    float* out     = (float*)d_out;
    float* zq      = out;
    float* pscalar = out + ZQ_SIZE;
    float* prob    = pscalar + 1;
    float* logp    = prob + PROB_SIZE;

    uint32_t kg1_0, kg1_1, kg2_0, kg2_1;
    h_tf(0u, 42u, 0u, 0u, &kg1_0, &kg1_1);
    h_tf(0u, 42u, 0u, 1u, &kg2_0, &kg2_1);

    k_scalars<<<1, 1>>>(lpq, lpqc, pscalar);
    k_cprobs<<<1, 256>>>(c_logits, kg1_0, kg1_1);
    k_norms<<<96, 256>>>(ze, books);
    k_split<<<1024, 256>>>(ze, books);
    k_gemm1_bf<<<dim3(KS_ / 128, M_TOT / 128), 256>>>();
    k_soft<<<dim3(N_, B_), 256>>>(prob, logp, kg2_0, kg2_1);
    k_gemm2_bf<<<dim3(D_ / 128, M_TOT / 128), 256>>>(zq);
}